// round 10
// baseline (speedup 1.0000x reference)
#include <cuda_runtime.h>
#include <cuda_bf16.h>
#include <math.h>
#include <stdint.h>

typedef unsigned int uint32;
typedef unsigned long long uint64;

// ---------------- problem constants ----------------
#define BATCH 16
#define SEQL  513
#define DMODEL 768
#define NHEAD 12
#define DHEAD 64
#define FFDIM 3072
#define NLAYER 12
#define NPATCH1 512
#define NPATCH2 128
#define PATCHE 256
#define STLEN 385
#define TOKENS (BATCH*SEQL)     // 8208
#define NBH (BATCH*NHEAD)       // 192
#define SPAD 640                // padded key stride (5*128)

// ---------------- scratch (device globals; no runtime alloc) ----------------
__device__ float g_z  [TOKENS*DMODEL];
__device__ float g_att[(size_t)NBH*SEQL*SPAD];      // logits fp32 [bh][q][SPAD]
__device__ float g_ff [TOKENS*FFDIM];               // embed scratch (fp32)
__device__ float g_pool[BATCH*DMODEL];
__device__ float g_hln [BATCH*DMODEL];
__device__ float g_h1  [BATCH*256];
__device__ float g_h2  [BATCH*64];

// bf16 split activations
__device__ __nv_bfloat16 g_ln_h[TOKENS*DMODEL];
__device__ __nv_bfloat16 g_ln_l[TOKENS*DMODEL];
__device__ __nv_bfloat16 g_ff_h[TOKENS*FFDIM];
__device__ __nv_bfloat16 g_ff_l[TOKENS*FFDIM];
// attention bf16 splits
__device__ __nv_bfloat16 g_qh[NBH*SEQL*DHEAD], g_ql[NBH*SEQL*DHEAD];
__device__ __nv_bfloat16 g_kh[NBH*SEQL*DHEAD], g_kl[NBH*SEQL*DHEAD];
__device__ __nv_bfloat16 g_vh[NBH*SPAD*DHEAD], g_vl[NBH*SPAD*DHEAD];   // zero-padded rows
__device__ __nv_bfloat16 g_ph[(size_t)NBH*SEQL*SPAD], g_pl[(size_t)NBH*SEQL*SPAD];
// split weights (original [K][N] layout): bf16 hi/lo
__device__ __nv_bfloat16 g_wqkv_h[NLAYER*DMODEL*3*DMODEL];
__device__ __nv_bfloat16 g_wqkv_l[NLAYER*DMODEL*3*DMODEL];
__device__ __nv_bfloat16 g_fc1_h[NLAYER*DMODEL*FFDIM];
__device__ __nv_bfloat16 g_fc1_l[NLAYER*DMODEL*FFDIM];
__device__ __nv_bfloat16 g_fc2_h[NLAYER*FFDIM*DMODEL];
__device__ __nv_bfloat16 g_fc2_l[NLAYER*FFDIM*DMODEL];
// embed splits
__device__ __nv_bfloat16 g_in1h[BATCH*NPATCH1*PATCHE], g_in1l[BATCH*NPATCH1*PATCHE];
__device__ __nv_bfloat16 g_in2h[BATCH*NPATCH2*PATCHE], g_in2l[BATCH*NPATCH2*PATCHE];
__device__ __nv_bfloat16 g_pwh[PATCHE*DMODEL], g_pwl[PATCHE*DMODEL];

// ---------------- helpers ----------------
__device__ __forceinline__ uint32 smaddr(const void* p) {
    return (uint32)__cvta_generic_to_shared(p);
}
__device__ __forceinline__ void ldmx4(uint32* r, uint32 a) {
    asm volatile("ldmatrix.sync.aligned.m8n8.x4.shared.b16 {%0,%1,%2,%3}, [%4];"
        : "=r"(r[0]), "=r"(r[1]), "=r"(r[2]), "=r"(r[3]) : "r"(a));
}
__device__ __forceinline__ void ldmx2t(uint32* r, uint32 a) {
    asm volatile("ldmatrix.sync.aligned.m8n8.x2.trans.shared.b16 {%0,%1}, [%2];"
        : "=r"(r[0]), "=r"(r[1]) : "r"(a));
}
__device__ __forceinline__ void ldmx2(uint32* r, uint32 a) {
    asm volatile("ldmatrix.sync.aligned.m8n8.x2.shared.b16 {%0,%1}, [%2];"
        : "=r"(r[0]), "=r"(r[1]) : "r"(a));
}
__device__ __forceinline__ void mma16816(float* c, const uint32* a, const uint32* b) {
    asm volatile(
        "mma.sync.aligned.m16n8k16.row.col.f32.bf16.bf16.f32 "
        "{%0,%1,%2,%3}, {%4,%5,%6,%7}, {%8,%9}, {%0,%1,%2,%3};"
        : "+f"(c[0]), "+f"(c[1]), "+f"(c[2]), "+f"(c[3])
        : "r"(a[0]), "r"(a[1]), "r"(a[2]), "r"(a[3]), "r"(b[0]), "r"(b[1]));
}
__device__ __forceinline__ void cpasync16(uint32 dst, const void* src, bool valid) {
    int sz = valid ? 16 : 0;
    asm volatile("cp.async.cg.shared.global [%0], [%1], 16, %2;"
        :: "r"(dst), "l"(src), "r"(sz) : "memory");
}

// ---------------- split fp32 -> (bf16 hi, bf16 lo) ----------------
__global__ __launch_bounds__(256) void split_k(
    const float* __restrict__ x, __nv_bfloat16* __restrict__ h,
    __nv_bfloat16* __restrict__ l, int n)
{
    int i = blockIdx.x * 256 + threadIdx.x;
    if (i >= n) return;
    float v = x[i];
    __nv_bfloat16 hi = __float2bfloat16(v);
    h[i] = hi;
    l[i] = __float2bfloat16(v - __bfloat162float(hi));
}

// ---------------- split-bf16 tensor-core GEMM, 3-stage cp.async pipeline ----
// C[M,N] = (Ah+Al)[M,K] @ (Bh+Bl)[K,N] via hh+lh+hl MMAs (term-major ILP).
// K % 32 == 0, N % 128 == 0. M ragged OK.
// qkv_mode: scatter outputs directly into split q/k/v buffers (N must be 2304).
#define MG_STAGE 37888
#define MG_SMEM  (3*MG_STAGE)
__global__ __launch_bounds__(256) void mma_gemm(
    const __nv_bfloat16* __restrict__ Ah, const __nv_bfloat16* __restrict__ Al,
    const __nv_bfloat16* __restrict__ Bh, const __nv_bfloat16* __restrict__ Bl,
    float* __restrict__ C, const float* __restrict__ bias,
    const float* __restrict__ res,
    __nv_bfloat16* __restrict__ Chi, __nv_bfloat16* __restrict__ Clo,
    int M, int N, int K, int act, int qkv_mode)
{
    extern __shared__ char smem[];
    const int tid = threadIdx.x;
    const int wid = tid >> 5, lane = tid & 31;
    const int warp_m = wid >> 2;            // 0..1  (64 rows each)
    const int warp_n = wid & 3;             // 0..3  (32 cols each)
    const int row0 = blockIdx.y * 128, col0 = blockIdx.x * 128;

    float acc[4][4][4];
#pragma unroll
    for (int i = 0; i < 4; i++)
#pragma unroll
        for (int j = 0; j < 4; j++)
#pragma unroll
            for (int e = 0; e < 4; e++) acc[i][j][e] = 0.f;

    const int nc = K >> 5;      // number of k32 chunks

#define MG_PREFETCH(CH) do {                                                  \
        int _st = (CH) % 3; int _k0 = (CH) << 5;                              \
        char* _sb = smem + _st * MG_STAGE;                                    \
        _Pragma("unroll")                                                     \
        for (int _i = 0; _i < 2; _i++) {                                      \
            int _idx = _i * 256 + tid;                                        \
            int _ar = _idx >> 2, _ac = _idx & 3;                              \
            int _gr = row0 + _ar;                                             \
            bool _v = _gr < M;                                                \
            size_t _ao = (size_t)(_v ? _gr : 0) * K + _k0 + _ac * 8;          \
            uint32 _da = smaddr(_sb + _ar * 80 + _ac * 16);                   \
            cpasync16(_da,         Ah + _ao, _v);                             \
            cpasync16(_da + 10240, Al + _ao, _v);                             \
            int _br = _idx >> 4, _bc = _idx & 15;                             \
            size_t _bo = (size_t)(_k0 + _br) * N + col0 + _bc * 8;            \
            uint32 _db = smaddr(_sb + 20480 + _br * 272 + _bc * 16);          \
            cpasync16(_db,        Bh + _bo, true);                            \
            cpasync16(_db + 8704, Bl + _bo, true);                            \
        }                                                                     \
        asm volatile("cp.async.commit_group;" ::: "memory");                  \
    } while (0)

    MG_PREFETCH(0);
    if (nc > 1) MG_PREFETCH(1);

    for (int ch = 0; ch < nc; ch++) {
        if (ch + 2 < nc) {
            MG_PREFETCH(ch + 2);
            asm volatile("cp.async.wait_group 2;" ::: "memory");
        } else if (ch + 1 < nc) {
            asm volatile("cp.async.wait_group 1;" ::: "memory");
        } else {
            asm volatile("cp.async.wait_group 0;" ::: "memory");
        }
        __syncthreads();

        char* sb = smem + (ch % 3) * MG_STAGE;
#pragma unroll
        for (int kk = 0; kk < 32; kk += 16) {
            // hoist ALL fragments (term-major ILP)
            uint32 bfh[4][2], bfl[4][2];
            int br = kk + (lane & 7) + (((lane >> 3) & 1) << 3);
#pragma unroll
            for (int nt = 0; nt < 4; nt++) {
                int bc = warp_n * 32 + nt * 8;
                uint32 ba = smaddr(sb + 20480 + br * 272 + bc * 2);
                ldmx2t(bfh[nt], ba);
                ldmx2t(bfl[nt], ba + 8704);
            }
            uint32 afh[4][4], afl[4][4];
#pragma unroll
            for (int mt = 0; mt < 4; mt++) {
                int ar = warp_m * 64 + mt * 16 + (lane & 15);
                int ac = kk + ((lane >> 4) << 3);
                uint32 aa = smaddr(sb + ar * 80 + ac * 2);
                ldmx4(afh[mt], aa);
                ldmx4(afl[mt], aa + 10240);
            }
            // term hh: 16 independent MMAs
#pragma unroll
            for (int mt = 0; mt < 4; mt++)
#pragma unroll
                for (int nt = 0; nt < 4; nt++)
                    mma16816(acc[mt][nt], afh[mt], bfh[nt]);
            // term lh
#pragma unroll
            for (int mt = 0; mt < 4; mt++)
#pragma unroll
                for (int nt = 0; nt < 4; nt++)
                    mma16816(acc[mt][nt], afl[mt], bfh[nt]);
            // term hl
#pragma unroll
            for (int mt = 0; mt < 4; mt++)
#pragma unroll
                for (int nt = 0; nt < 4; nt++)
                    mma16816(acc[mt][nt], afh[mt], bfl[nt]);
        }
        __syncthreads();
    }

    // epilogue
#pragma unroll
    for (int mt = 0; mt < 4; mt++) {
#pragma unroll
        for (int g = 0; g < 2; g++) {
            int r = row0 + warp_m * 64 + mt * 16 + (lane >> 2) + g * 8;
            if (r >= M) continue;
            int b_ = r / SEQL, n_ = r - b_ * SEQL;    // for qkv_mode
#pragma unroll
            for (int nt = 0; nt < 4; nt++) {
                int cbase = col0 + warp_n * 32 + nt * 8 + ((lane & 3) << 1);
#pragma unroll
                for (int t = 0; t < 2; t++) {
                    int c = cbase + t;
                    float v = acc[mt][nt][g * 2 + t];
                    if (qkv_mode) {
                        int h = c / 192, rem = c - h * 192;
                        int d = rem / 3, which = rem - 3 * d;
                        int bh = b_ * NHEAD + h;
                        __nv_bfloat16 hi = __float2bfloat16(v);
                        __nv_bfloat16 lo = __float2bfloat16(v - __bfloat162float(hi));
                        if (which == 0) {
                            size_t qi = ((size_t)bh * SEQL + n_) * DHEAD + d;
                            g_qh[qi] = hi; g_ql[qi] = lo;
                        } else if (which == 1) {
                            size_t ki = ((size_t)bh * SEQL + n_) * DHEAD + d;
                            g_kh[ki] = hi; g_kl[ki] = lo;
                        } else {
                            size_t vi = ((size_t)bh * SPAD + n_) * DHEAD + d;
                            g_vh[vi] = hi; g_vl[vi] = lo;
                        }
                        continue;
                    }
                    if (bias) v += bias[c];
                    if (act)  v = v * normcdff(v);     // exact GELU
                    if (res)  v += res[(size_t)r * N + c];
                    size_t o = (size_t)r * N + c;
                    if (C) C[o] = v;
                    if (Chi) {
                        __nv_bfloat16 hi = __float2bfloat16(v);
                        Chi[o] = hi;
                        Clo[o] = __float2bfloat16(v - __bfloat162float(hi));
                    }
                }
            }
        }
    }
}

// ---------------- attention scores: S = Q K^T / 8  (split-bf16 HMMA) ----
#define SC_SMEM (4*128*144)
__global__ __launch_bounds__(256) void attn_scores_mma()
{
    extern __shared__ char smem[];
    const int tid = threadIdx.x;
    const int wid = tid >> 5, lane = tid & 31;
    const int warp_m = wid >> 2;            // 0..1 (64 q-rows)
    const int warp_n = wid & 3;             // 0..3 (32 keys)
    const int key0 = blockIdx.x * 128, q0 = blockIdx.y * 128;
    const int bh = blockIdx.z;

    char* Qh = smem;
    char* Kh = smem + 36864;

#pragma unroll
    for (int i = 0; i < 4; i++) {
        int idx = i * 256 + tid;          // 0..1023
        int ar = idx >> 3, ac = idx & 7;  // row 0..127, chunk 0..7
        int qr = q0 + ar;
        bool vq = qr < SEQL;
        size_t qo = ((size_t)bh * SEQL + (vq ? qr : 0)) * DHEAD + ac * 8;
        uint32 dq = smaddr(Qh + ar * 144 + ac * 16);
        cpasync16(dq,         g_qh + qo, vq);
        cpasync16(dq + 18432, g_ql + qo, vq);
        int kr = key0 + ar;
        bool vk = kr < SEQL;
        size_t ko = ((size_t)bh * SEQL + (vk ? kr : 0)) * DHEAD + ac * 8;
        uint32 dk = smaddr(Kh + ar * 144 + ac * 16);
        cpasync16(dk,         g_kh + ko, vk);
        cpasync16(dk + 18432, g_kl + ko, vk);
    }
    asm volatile("cp.async.commit_group;" ::: "memory");
    asm volatile("cp.async.wait_group 0;" ::: "memory");
    __syncthreads();

    float acc[4][4][4];
#pragma unroll
    for (int i = 0; i < 4; i++)
#pragma unroll
        for (int j = 0; j < 4; j++)
#pragma unroll
            for (int e = 0; e < 4; e++) acc[i][j][e] = 0.f;

#pragma unroll
    for (int kk = 0; kk < 64; kk += 16) {
        uint32 bfh[4][2], bfl[4][2];
        int koff = kk + (((lane >> 3) & 1) << 3);
#pragma unroll
        for (int nt = 0; nt < 4; nt++) {
            int nr = warp_n * 32 + nt * 8 + (lane & 7);
            uint32 ba = smaddr(Kh + nr * 144 + koff * 2);
            ldmx2(bfh[nt], ba);
            ldmx2(bfl[nt], ba + 18432);
        }
        uint32 afh[4][4], afl[4][4];
#pragma unroll
        for (int mt = 0; mt < 4; mt++) {
            int ar = warp_m * 64 + mt * 16 + (lane & 15);
            int ac = kk + ((lane >> 4) << 3);
            uint32 aa = smaddr(Qh + ar * 144 + ac * 2);
            ldmx4(afh[mt], aa);
            ldmx4(afl[mt], aa + 18432);
        }
#pragma unroll
        for (int mt = 0; mt < 4; mt++)
#pragma unroll
            for (int nt = 0; nt < 4; nt++)
                mma16816(acc[mt][nt], afh[mt], bfh[nt]);
#pragma unroll
        for (int mt = 0; mt < 4; mt++)
#pragma unroll
            for (int nt = 0; nt < 4; nt++)
                mma16816(acc[mt][nt], afl[mt], bfh[nt]);
#pragma unroll
        for (int mt = 0; mt < 4; mt++)
#pragma unroll
            for (int nt = 0; nt < 4; nt++)
                mma16816(acc[mt][nt], afh[mt], bfl[nt]);
    }

    float* S = g_att + (size_t)bh * SEQL * SPAD;
#pragma unroll
    for (int mt = 0; mt < 4; mt++) {
#pragma unroll
        for (int g = 0; g < 2; g++) {
            int r = q0 + warp_m * 64 + mt * 16 + (lane >> 2) + g * 8;
            if (r >= SEQL) continue;
#pragma unroll
            for (int nt = 0; nt < 4; nt++) {
                int cbase = key0 + warp_n * 32 + nt * 8 + ((lane & 3) << 1);
#pragma unroll
                for (int t = 0; t < 2; t++) {
                    int c = cbase + t;
                    if (c < SEQL)
                        S[(size_t)r * SPAD + c] = acc[mt][nt][g * 2 + t] * 0.125f;
                }
            }
        }
    }
}

// ---------------- softmax: fp32 logits -> split bf16 probs (padded zeros) ----
__global__ __launch_bounds__(128) void softmax_k()
{
    size_t row = blockIdx.x;
    const float* p = g_att + row * SPAD;
    __nv_bfloat16* ph = g_ph + row * SPAD;
    __nv_bfloat16* pl = g_pl + row * SPAD;
    int tid = threadIdx.x;
    float vals[5];
    int cnt = 0;
    float lmax = -3.4e38f;
    for (int i = tid; i < SEQL; i += 128) { float v = p[i]; vals[cnt++] = v; lmax = fmaxf(lmax, v); }
#pragma unroll
    for (int o = 16; o; o >>= 1) lmax = fmaxf(lmax, __shfl_xor_sync(0xffffffffu, lmax, o));
    __shared__ float sm[4], ss[4];
    if ((tid & 31) == 0) sm[tid >> 5] = lmax;
    __syncthreads();
    lmax = fmaxf(fmaxf(sm[0], sm[1]), fmaxf(sm[2], sm[3]));
    float lsum = 0.f;
    for (int j = 0; j < cnt; j++) { vals[j] = expf(vals[j] - lmax); lsum += vals[j]; }
#pragma unroll
    for (int o = 16; o; o >>= 1) lsum += __shfl_xor_sync(0xffffffffu, lsum, o);
    if ((tid & 31) == 0) ss[tid >> 5] = lsum;
    __syncthreads();
    lsum = ss[0] + ss[1] + ss[2] + ss[3];
    float inv = 1.f / lsum;
    cnt = 0;
    for (int i = tid; i < SEQL; i += 128) {
        float v = vals[cnt++] * inv;
        __nv_bfloat16 hi = __float2bfloat16(v);
        ph[i] = hi;
        pl[i] = __float2bfloat16(v - __bfloat162float(hi));
    }
    for (int i = SEQL + tid; i < SPAD; i += 128) { ph[i] = __float2bfloat16(0.f); pl[i] = __float2bfloat16(0.f); }
}

// ---------------- AV: Z += P @ V  (split-bf16 HMMA, fused residual add) ----
#define AV_SMEM (2*128*272 + 2*128*144)
__global__ __launch_bounds__(256) void attn_av_mma()
{
    extern __shared__ char smem[];
    const int tid = threadIdx.x;
    const int wid = tid >> 5, lane = tid & 31;
    const int warp_m = wid & 3;             // 0..3 (32 q-rows)
    const int warp_n = wid >> 2;            // 0..1 (32 d-cols)
    const int q0 = blockIdx.x * 128;
    const int bh = blockIdx.y;

    char* Ph = smem;
    char* Vh = smem + 69632;

    float acc[2][4][4];
#pragma unroll
    for (int i = 0; i < 2; i++)
#pragma unroll
        for (int j = 0; j < 4; j++)
#pragma unroll
            for (int e = 0; e < 4; e++) acc[i][j][e] = 0.f;

    for (int kt = 0; kt < 5; kt++) {
#pragma unroll
        for (int i = 0; i < 8; i++) {
            int idx = i * 256 + tid;
            int ar = idx >> 4, ac = idx & 15;
            int qr = q0 + ar;
            bool v = qr < SEQL;
            size_t po = ((size_t)bh * SEQL + (v ? qr : 0)) * SPAD + kt * 128 + ac * 8;
            uint32 dp = smaddr(Ph + ar * 272 + ac * 16);
            cpasync16(dp,         g_ph + po, v);
            cpasync16(dp + 34816, g_pl + po, v);
        }
#pragma unroll
        for (int i = 0; i < 4; i++) {
            int idx = i * 256 + tid;          // 0..1023
            int ar = idx >> 3, ac = idx & 7;
            size_t vo = ((size_t)bh * SPAD + kt * 128 + ar) * DHEAD + ac * 8;
            uint32 dv = smaddr(Vh + ar * 144 + ac * 16);
            cpasync16(dv,         g_vh + vo, true);
            cpasync16(dv + 18432, g_vl + vo, true);
        }
        asm volatile("cp.async.commit_group;" ::: "memory");
        asm volatile("cp.async.wait_group 0;" ::: "memory");
        __syncthreads();

#pragma unroll
        for (int kk = 0; kk < 128; kk += 16) {
            uint32 bfh[4][2], bfl[4][2];
            int br = kk + (lane & 7) + (((lane >> 3) & 1) << 3);
#pragma unroll
            for (int nt = 0; nt < 4; nt++) {
                int bc = warp_n * 32 + nt * 8;
                uint32 ba = smaddr(Vh + br * 144 + bc * 2);
                ldmx2t(bfh[nt], ba);
                ldmx2t(bfl[nt], ba + 18432);
            }
            uint32 afh[2][4], afl[2][4];
#pragma unroll
            for (int mt = 0; mt < 2; mt++) {
                int ar = warp_m * 32 + mt * 16 + (lane & 15);
                int ac = kk + ((lane >> 4) << 3);
                uint32 aa = smaddr(Ph + ar * 272 + ac * 2);
                ldmx4(afh[mt], aa);
                ldmx4(afl[mt], aa + 34816);
            }
#pragma unroll
            for (int mt = 0; mt < 2; mt++)
#pragma unroll
                for (int nt = 0; nt < 4; nt++)
                    mma16816(acc[mt][nt], afh[mt], bfh[nt]);
#pragma unroll
            for (int mt = 0; mt < 2; mt++)
#pragma unroll
                for (int nt = 0; nt < 4; nt++)
                    mma16816(acc[mt][nt], afl[mt], bfh[nt]);
#pragma unroll
            for (int mt = 0; mt < 2; mt++)
#pragma unroll
                for (int nt = 0; nt < 4; nt++)
                    mma16816(acc[mt][nt], afh[mt], bfl[nt]);
        }
        __syncthreads();
    }

    // epilogue: fused residual add into g_z
    int b = bh / NHEAD, h = bh % NHEAD;
#pragma unroll
    for (int mt = 0; mt < 2; mt++) {
#pragma unroll
        for (int g = 0; g < 2; g++) {
            int r = q0 + warp_m * 32 + mt * 16 + (lane >> 2) + g * 8;
            if (r >= SEQL) continue;
            size_t zbase = ((size_t)(b * SEQL + r)) * DMODEL + h * DHEAD;
#pragma unroll
            for (int nt = 0; nt < 4; nt++) {
                int cbase = warp_n * 32 + nt * 8 + ((lane & 3) << 1);
#pragma unroll
                for (int t = 0; t < 2; t++)
                    g_z[zbase + cbase + t] += acc[mt][nt][g * 2 + t];
            }
        }
    }
}

// ---------------- layernorm: writes bf16 hi/lo ----------------
__global__ __launch_bounds__(256) void layernorm_split_k(
    const float* __restrict__ x, __nv_bfloat16* __restrict__ yh,
    __nv_bfloat16* __restrict__ yl,
    const float* __restrict__ s, const float* __restrict__ b)
{
    int row = blockIdx.x;
    const float* xr = x + (size_t)row * DMODEL;
    int tid = threadIdx.x;
    float v0 = xr[tid], v1 = xr[tid + 256], v2 = xr[tid + 512];
    float sum = v0 + v1 + v2;
    float sq  = fmaf(v0, v0, fmaf(v1, v1, v2 * v2));
#pragma unroll
    for (int o = 16; o; o >>= 1) {
        sum += __shfl_xor_sync(0xffffffffu, sum, o);
        sq  += __shfl_xor_sync(0xffffffffu, sq,  o);
    }
    __shared__ float s1[8], s2[8];
    if ((tid & 31) == 0) { s1[tid >> 5] = sum; s2[tid >> 5] = sq; }
    __syncthreads();
    float tsum = 0.f, tsq = 0.f;
#pragma unroll
    for (int i = 0; i < 8; i++) { tsum += s1[i]; tsq += s2[i]; }
    float m = tsum * (1.f / DMODEL);
    float var = tsq * (1.f / DMODEL) - m * m;
    float r = rsqrtf(var + 1e-5f);
    size_t base = (size_t)row * DMODEL;
#pragma unroll
    for (int p = 0; p < 3; p++) {
        int i = tid + p * 256;
        float v = (p == 0 ? v0 : (p == 1 ? v1 : v2));
        float y = (v - m) * r * s[i] + b[i];
        __nv_bfloat16 hi = __float2bfloat16(y);
        yh[base + i] = hi;
        yl[base + i] = __float2bfloat16(y - __bfloat162float(hi));
    }
}

// fp32-output layernorm (head)
__global__ __launch_bounds__(256) void layernorm_k(
    const float* __restrict__ x, float* __restrict__ y,
    const float* __restrict__ s, const float* __restrict__ b)
{
    int row = blockIdx.x;
    const float* xr = x + (size_t)row * DMODEL;
    float* yr = y + (size_t)row * DMODEL;
    int tid = threadIdx.x;
    float v0 = xr[tid], v1 = xr[tid + 256], v2 = xr[tid + 512];
    float sum = v0 + v1 + v2;
    float sq  = fmaf(v0, v0, fmaf(v1, v1, v2 * v2));
#pragma unroll
    for (int o = 16; o; o >>= 1) {
        sum += __shfl_xor_sync(0xffffffffu, sum, o);
        sq  += __shfl_xor_sync(0xffffffffu, sq,  o);
    }
    __shared__ float s1[8], s2[8];
    if ((tid & 31) == 0) { s1[tid >> 5] = sum; s2[tid >> 5] = sq; }
    __syncthreads();
    float tsum = 0.f, tsq = 0.f;
#pragma unroll
    for (int i = 0; i < 8; i++) { tsum += s1[i]; tsq += s2[i]; }
    float m = tsum * (1.f / DMODEL);
    float var = tsq * (1.f / DMODEL) - m * m;
    float r = rsqrtf(var + 1e-5f);
    yr[tid]       = (v0 - m) * r * s[tid]       + b[tid];
    yr[tid + 256] = (v1 - m) * r * s[tid + 256] + b[tid + 256];
    yr[tid + 512] = (v2 - m) * r * s[tid + 512] + b[tid + 512];
}

// ---------------- embed assemble ----------------
__global__ __launch_bounds__(256) void assemble_k(
    const float* __restrict__ pos_emb, const float* __restrict__ strain_emb,
    const float* __restrict__ cls_token)
{
    int idx = blockIdx.x * 256 + threadIdx.x;
    int bt = idx / DMODEL;
    int d = idx - bt * DMODEL;
    int b = bt / SEQL;
    int t = bt - b * SEQL;
    float v = pos_emb[(size_t)t * DMODEL + d];
    if (t < STLEN) v += strain_emb[(size_t)t * DMODEL + d];
    else           v += g_ff[((size_t)(8192 + b * NPATCH2 + (t - STLEN))) * DMODEL + d];
    if (t == 0)    v += cls_token[d];
    else           v += g_ff[((size_t)(b * NPATCH1 + (t - 1))) * DMODEL + d];
    g_z[idx] = v;
}

// ---------------- mean pool over tokens ----------------
__global__ __launch_bounds__(256) void pool_k()
{
    int idx = blockIdx.x * 256 + threadIdx.x;
    int b = idx / DMODEL, d = idx - b * DMODEL;
    const float* p = g_z + (size_t)b * SEQL * DMODEL + d;
    float s = 0.f;
    for (int n = 0; n < SEQL; n++) s += p[(size_t)n * DMODEL];
    g_pool[idx] = s * (1.f / SEQL);
}

// ---------------- tiny head GEMM ----------------
__global__ void small_gemm_k(const float* __restrict__ A, const float* __restrict__ W,
                             const float* __restrict__ bias, float* __restrict__ C,
                             int N, int K)
{
    int m = blockIdx.x, n = threadIdx.x;
    if (n >= N) return;
    float s = bias[n];
    const float* a = A + (size_t)m * K;
    for (int k = 0; k < K; k++) s = fmaf(a[k], W[(size_t)k * N + n], s);
    C[(size_t)m * N + n] = s;
}

// ---------------- launch ----------------
extern "C" void kernel_launch(void* const* d_in, const int* in_sizes, int n_in,
                              void* d_out, int out_size)
{
    const float* input1     = (const float*)d_in[0];
    const float* input2     = (const float*)d_in[1];
    const float* proj_w     = (const float*)d_in[2];
    const float* proj_b     = (const float*)d_in[3];
    const float* cls_token  = (const float*)d_in[4];
    const float* pos_emb    = (const float*)d_in[5];
    const float* strain_emb = (const float*)d_in[6];
    const float* ln1_s      = (const float*)d_in[7];
    const float* ln1_b      = (const float*)d_in[8];
    const float* wqkv       = (const float*)d_in[9];
    const float* ln2_s      = (const float*)d_in[10];
    const float* ln2_b      = (const float*)d_in[11];
    const float* fc1_w      = (const float*)d_in[12];
    const float* fc1_b      = (const float*)d_in[13];
    const float* fc2_w      = (const float*)d_in[14];
    const float* fc2_b      = (const float*)d_in[15];
    const float* hn_s       = (const float*)d_in[16];
    const float* hn_b       = (const float*)d_in[17];
    const float* h1_w       = (const float*)d_in[18];
    const float* h1_b       = (const float*)d_in[19];
    const float* h2_w       = (const float*)d_in[20];
    const float* h2_b       = (const float*)d_in[21];
    const float* h3_w       = (const float*)d_in[22];
    const float* h3_b       = (const float*)d_in[23];

    float *z, *ff, *pool, *hln, *h1, *h2;
    __nv_bfloat16 *lnh, *lnl, *ffh, *ffl, *wqh, *wql, *f1h, *f1l, *f2h, *f2l;
    __nv_bfloat16 *i1h, *i1l, *i2h, *i2l, *pwh, *pwl;
    cudaGetSymbolAddress((void**)&z,    g_z);
    cudaGetSymbolAddress((void**)&ff,   g_ff);
    cudaGetSymbolAddress((void**)&pool, g_pool);
    cudaGetSymbolAddress((void**)&hln,  g_hln);
    cudaGetSymbolAddress((void**)&h1,   g_h1);
    cudaGetSymbolAddress((void**)&h2,   g_h2);
    cudaGetSymbolAddress((void**)&lnh,  g_ln_h);
    cudaGetSymbolAddress((void**)&lnl,  g_ln_l);
    cudaGetSymbolAddress((void**)&ffh,  g_ff_h);
    cudaGetSymbolAddress((void**)&ffl,  g_ff_l);
    cudaGetSymbolAddress((void**)&wqh,  g_wqkv_h);
    cudaGetSymbolAddress((void**)&wql,  g_wqkv_l);
    cudaGetSymbolAddress((void**)&f1h,  g_fc1_h);
    cudaGetSymbolAddress((void**)&f1l,  g_fc1_l);
    cudaGetSymbolAddress((void**)&f2h,  g_fc2_h);
    cudaGetSymbolAddress((void**)&f2l,  g_fc2_l);
    cudaGetSymbolAddress((void**)&i1h,  g_in1h);
    cudaGetSymbolAddress((void**)&i1l,  g_in1l);
    cudaGetSymbolAddress((void**)&i2h,  g_in2h);
    cudaGetSymbolAddress((void**)&i2l,  g_in2l);
    cudaGetSymbolAddress((void**)&pwh,  g_pwh);
    cudaGetSymbolAddress((void**)&pwl,  g_pwl);

    cudaFuncSetAttribute(mma_gemm, cudaFuncAttributeMaxDynamicSharedMemorySize, MG_SMEM);
    cudaFuncSetAttribute(attn_scores_mma, cudaFuncAttributeMaxDynamicSharedMemorySize, SC_SMEM);
    cudaFuncSetAttribute(attn_av_mma, cudaFuncAttributeMaxDynamicSharedMemorySize, AV_SMEM);

    const int TOK = TOKENS;
    const int ELEM_BLKS = (TOK * DMODEL) / 256;

    // ---- input / proj_w splits, then patch embed MMA (profiled slot) ----
    {
        int ni1 = BATCH * NPATCH1 * PATCHE;
        int ni2 = BATCH * NPATCH2 * PATCHE;
        int npw = PATCHE * DMODEL;
        split_k<<<(ni1 + 255) / 256, 256>>>(input1, i1h, i1l, ni1);
        split_k<<<(ni2 + 255) / 256, 256>>>(input2, i2h, i2l, ni2);
        split_k<<<(npw + 255) / 256, 256>>>(proj_w, pwh, pwl, npw);
    }
    mma_gemm<<<dim3(DMODEL / 128, (BATCH * NPATCH1) / 128), 256, MG_SMEM>>>(
        i1h, i1l, pwh, pwl, ff, proj_b, nullptr, nullptr, nullptr,
        BATCH * NPATCH1, DMODEL, PATCHE, 0, 0);
    mma_gemm<<<dim3(DMODEL / 128, (BATCH * NPATCH2) / 128), 256, MG_SMEM>>>(
        i2h, i2l, pwh, pwl, ff + (size_t)BATCH * NPATCH1 * DMODEL, proj_b, nullptr,
        nullptr, nullptr, BATCH * NPATCH2, DMODEL, PATCHE, 0, 0);

    // ---- weight splits ----
    {
        int n1 = NLAYER * DMODEL * 3 * DMODEL;
        int n2 = NLAYER * DMODEL * FFDIM;
        split_k<<<(n1 + 255) / 256, 256>>>(wqkv,  wqh, wql, n1);
        split_k<<<(n2 + 255) / 256, 256>>>(fc1_w, f1h, f1l, n2);
        split_k<<<(n2 + 255) / 256, 256>>>(fc2_w, f2h, f2l, n2);
    }

    assemble_k<<<ELEM_BLKS, 256>>>(pos_emb, strain_emb, cls_token);

    const int MB = (TOK + 127) / 128;   // 65
    const int QT = (SEQL + 127) / 128;  // 5

    // ---- transformer layers ----
    for (int l = 0; l < NLAYER; l++) {
        layernorm_split_k<<<TOK, 256>>>(z, lnh, lnl, ln1_s + l * DMODEL, ln1_b + l * DMODEL);
        mma_gemm<<<dim3((3 * DMODEL) / 128, MB), 256, MG_SMEM>>>(
            lnh, lnl, wqh + (size_t)l * DMODEL * 3 * DMODEL, wql + (size_t)l * DMODEL * 3 * DMODEL,
            nullptr, nullptr, nullptr, nullptr, nullptr, TOK, 3 * DMODEL, DMODEL, 0, 1 /*qkv*/);
        attn_scores_mma<<<dim3(QT, QT, NBH), 256, SC_SMEM>>>();
        softmax_k<<<NBH * SEQL, 128>>>();
        attn_av_mma<<<dim3(QT, NBH), 256, AV_SMEM>>>();     // fused residual add
        layernorm_split_k<<<TOK, 256>>>(z, lnh, lnl, ln2_s + l * DMODEL, ln2_b + l * DMODEL);
        mma_gemm<<<dim3(FFDIM / 128, MB), 256, MG_SMEM>>>(
            lnh, lnl, f1h + (size_t)l * DMODEL * FFDIM, f1l + (size_t)l * DMODEL * FFDIM,
            nullptr, fc1_b + l * FFDIM, nullptr, ffh, ffl, TOK, FFDIM, DMODEL, 1, 0);
        mma_gemm<<<dim3(DMODEL / 128, MB), 256, MG_SMEM>>>(
            ffh, ffl, f2h + (size_t)l * FFDIM * DMODEL, f2l + (size_t)l * FFDIM * DMODEL,
            z, fc2_b + l * DMODEL, z, nullptr, nullptr, TOK, DMODEL, FFDIM, 0, 0);
    }

    // ---- head ----
    pool_k<<<(BATCH * DMODEL) / 256, 256>>>();
    layernorm_k<<<BATCH, 256>>>(pool, hln, hn_s, hn_b);
    small_gemm_k<<<BATCH, 256>>>(hln, h1_w, h1_b, h1, 256, DMODEL);
    small_gemm_k<<<BATCH, 64>>>(h1, h2_w, h2_b, h2, 64, 256);
    small_gemm_k<<<BATCH, 32>>>(h2, h3_w, h3_b, (float*)d_out, 1, 64);
}

// round 11
// speedup vs baseline: 1.1341x; 1.1341x over previous
#include <cuda_runtime.h>
#include <cuda_bf16.h>
#include <math.h>
#include <stdint.h>

typedef unsigned int uint32;
typedef unsigned long long uint64;

// ---------------- problem constants ----------------
#define BATCH 16
#define SEQL  513
#define DMODEL 768
#define NHEAD 12
#define DHEAD 64
#define FFDIM 3072
#define NLAYER 12
#define NPATCH1 512
#define NPATCH2 128
#define PATCHE 256
#define STLEN 385
#define TOKENS (BATCH*SEQL)     // 8208
#define NBH (BATCH*NHEAD)       // 192
#define SPAD 640                // padded key stride (5*128)

// ---------------- scratch (device globals; no runtime alloc) ----------------
__device__ float g_z  [TOKENS*DMODEL];
__device__ float g_qkv[TOKENS*3*DMODEL];
__device__ float g_att[(size_t)NBH*SEQL*SPAD];      // logits fp32 [bh][q][SPAD]
__device__ float g_ff [TOKENS*FFDIM];               // embed scratch (fp32)
__device__ float g_pool[BATCH*DMODEL];
__device__ float g_hln [BATCH*DMODEL];
__device__ float g_h1  [BATCH*256];
__device__ float g_h2  [BATCH*64];

// bf16 split activations
__device__ __nv_bfloat16 g_ln_h[TOKENS*DMODEL];
__device__ __nv_bfloat16 g_ln_l[TOKENS*DMODEL];
__device__ __nv_bfloat16 g_ff_h[TOKENS*FFDIM];
__device__ __nv_bfloat16 g_ff_l[TOKENS*FFDIM];
// attention bf16 splits
__device__ __nv_bfloat16 g_qh[NBH*SEQL*DHEAD], g_ql[NBH*SEQL*DHEAD];
__device__ __nv_bfloat16 g_kh[NBH*SEQL*DHEAD], g_kl[NBH*SEQL*DHEAD];
__device__ __nv_bfloat16 g_vh[NBH*SPAD*DHEAD], g_vl[NBH*SPAD*DHEAD];   // zero-padded rows
__device__ __nv_bfloat16 g_ph[(size_t)NBH*SEQL*SPAD], g_pl[(size_t)NBH*SEQL*SPAD];
// split weights (original [K][N] layout): bf16 hi/lo
__device__ __nv_bfloat16 g_wqkv_h[NLAYER*DMODEL*3*DMODEL];
__device__ __nv_bfloat16 g_wqkv_l[NLAYER*DMODEL*3*DMODEL];
__device__ __nv_bfloat16 g_fc1_h[NLAYER*DMODEL*FFDIM];
__device__ __nv_bfloat16 g_fc1_l[NLAYER*DMODEL*FFDIM];
__device__ __nv_bfloat16 g_fc2_h[NLAYER*FFDIM*DMODEL];
__device__ __nv_bfloat16 g_fc2_l[NLAYER*FFDIM*DMODEL];
// embed splits
__device__ __nv_bfloat16 g_in1h[BATCH*NPATCH1*PATCHE], g_in1l[BATCH*NPATCH1*PATCHE];
__device__ __nv_bfloat16 g_in2h[BATCH*NPATCH2*PATCHE], g_in2l[BATCH*NPATCH2*PATCHE];
__device__ __nv_bfloat16 g_pwh[PATCHE*DMODEL], g_pwl[PATCHE*DMODEL];

// ---------------- helpers ----------------
__device__ __forceinline__ uint32 smaddr(const void* p) {
    return (uint32)__cvta_generic_to_shared(p);
}
__device__ __forceinline__ void ldmx4(uint32* r, uint32 a) {
    asm volatile("ldmatrix.sync.aligned.m8n8.x4.shared.b16 {%0,%1,%2,%3}, [%4];"
        : "=r"(r[0]), "=r"(r[1]), "=r"(r[2]), "=r"(r[3]) : "r"(a));
}
__device__ __forceinline__ void ldmx2t(uint32* r, uint32 a) {
    asm volatile("ldmatrix.sync.aligned.m8n8.x2.trans.shared.b16 {%0,%1}, [%2];"
        : "=r"(r[0]), "=r"(r[1]) : "r"(a));
}
__device__ __forceinline__ void ldmx2(uint32* r, uint32 a) {
    asm volatile("ldmatrix.sync.aligned.m8n8.x2.shared.b16 {%0,%1}, [%2];"
        : "=r"(r[0]), "=r"(r[1]) : "r"(a));
}
__device__ __forceinline__ void mma16816(float* c, const uint32* a, const uint32* b) {
    asm volatile(
        "mma.sync.aligned.m16n8k16.row.col.f32.bf16.bf16.f32 "
        "{%0,%1,%2,%3}, {%4,%5,%6,%7}, {%8,%9}, {%0,%1,%2,%3};"
        : "+f"(c[0]), "+f"(c[1]), "+f"(c[2]), "+f"(c[3])
        : "r"(a[0]), "r"(a[1]), "r"(a[2]), "r"(a[3]), "r"(b[0]), "r"(b[1]));
}
__device__ __forceinline__ void cpasync16(uint32 dst, const void* src, bool valid) {
    int sz = valid ? 16 : 0;
    asm volatile("cp.async.cg.shared.global [%0], [%1], 16, %2;"
        :: "r"(dst), "l"(src), "r"(sz) : "memory");
}

// ---------------- split fp32 -> (bf16 hi, bf16 lo) ----------------
__global__ __launch_bounds__(256) void split_k(
    const float* __restrict__ x, __nv_bfloat16* __restrict__ h,
    __nv_bfloat16* __restrict__ l, int n)
{
    int i = blockIdx.x * 256 + threadIdx.x;
    if (i >= n) return;
    float v = x[i];
    __nv_bfloat16 hi = __float2bfloat16(v);
    h[i] = hi;
    l[i] = __float2bfloat16(v - __bfloat162float(hi));
}

// ---------------- split-bf16 tensor-core GEMM, 2-stage pipeline, 2 CTAs/SM ----
// C[M,N] = (Ah+Al)[M,K] @ (Bh+Bl)[K,N] via hh+lh+hl MMAs.
// K % 32 == 0, N % 128 == 0. M ragged OK.
#define MG_STAGE 37888
#define MG_SMEM  (2*MG_STAGE)
__global__ __launch_bounds__(256, 2) void mma_gemm(
    const __nv_bfloat16* __restrict__ Ah, const __nv_bfloat16* __restrict__ Al,
    const __nv_bfloat16* __restrict__ Bh, const __nv_bfloat16* __restrict__ Bl,
    float* __restrict__ C, const float* __restrict__ bias,
    const float* __restrict__ res,
    __nv_bfloat16* __restrict__ Chi, __nv_bfloat16* __restrict__ Clo,
    int M, int N, int K, int act)
{
    extern __shared__ char smem[];
    const int tid = threadIdx.x;
    const int wid = tid >> 5, lane = tid & 31;
    const int warp_m = wid >> 2;            // 0..1  (64 rows each)
    const int warp_n = wid & 3;             // 0..3  (32 cols each)
    const int row0 = blockIdx.y * 128, col0 = blockIdx.x * 128;

    float acc[4][4][4];
#pragma unroll
    for (int i = 0; i < 4; i++)
#pragma unroll
        for (int j = 0; j < 4; j++)
#pragma unroll
            for (int e = 0; e < 4; e++) acc[i][j][e] = 0.f;

    const int nc = K >> 5;      // number of k32 chunks

#define MG_PREFETCH(CH) do {                                                  \
        int _st = (CH) & 1; int _k0 = (CH) << 5;                              \
        char* _sb = smem + _st * MG_STAGE;                                    \
        _Pragma("unroll")                                                     \
        for (int _i = 0; _i < 2; _i++) {                                      \
            int _idx = _i * 256 + tid;                                        \
            int _ar = _idx >> 2, _ac = _idx & 3;                              \
            int _gr = row0 + _ar;                                             \
            bool _v = _gr < M;                                                \
            size_t _ao = (size_t)(_v ? _gr : 0) * K + _k0 + _ac * 8;          \
            uint32 _da = smaddr(_sb + _ar * 80 + _ac * 16);                   \
            cpasync16(_da,         Ah + _ao, _v);                             \
            cpasync16(_da + 10240, Al + _ao, _v);                             \
            int _br = _idx >> 4, _bc = _idx & 15;                             \
            size_t _bo = (size_t)(_k0 + _br) * N + col0 + _bc * 8;            \
            uint32 _db = smaddr(_sb + 20480 + _br * 272 + _bc * 16);          \
            cpasync16(_db,        Bh + _bo, true);                            \
            cpasync16(_db + 8704, Bl + _bo, true);                            \
        }                                                                     \
        asm volatile("cp.async.commit_group;" ::: "memory");                  \
    } while (0)

    MG_PREFETCH(0);

    for (int ch = 0; ch < nc; ch++) {
        if (ch + 1 < nc) {
            MG_PREFETCH(ch + 1);
            asm volatile("cp.async.wait_group 1;" ::: "memory");
        } else {
            asm volatile("cp.async.wait_group 0;" ::: "memory");
        }
        __syncthreads();

        char* sb = smem + (ch & 1) * MG_STAGE;
#pragma unroll
        for (int kk = 0; kk < 32; kk += 16) {
            uint32 bfh[4][2], bfl[4][2];
            int br = kk + (lane & 7) + (((lane >> 3) & 1) << 3);
#pragma unroll
            for (int nt = 0; nt < 4; nt++) {
                int bc = warp_n * 32 + nt * 8;
                uint32 ba = smaddr(sb + 20480 + br * 272 + bc * 2);
                ldmx2t(bfh[nt], ba);
                ldmx2t(bfl[nt], ba + 8704);
            }
#pragma unroll
            for (int mt = 0; mt < 4; mt++) {
                int ar = warp_m * 64 + mt * 16 + (lane & 15);
                int ac = kk + ((lane >> 4) << 3);
                uint32 aa = smaddr(sb + ar * 80 + ac * 2);
                uint32 afh[4], afl[4];
                ldmx4(afh, aa);
                ldmx4(afl, aa + 10240);
#pragma unroll
                for (int nt = 0; nt < 4; nt++) {
                    mma16816(acc[mt][nt], afh, bfh[nt]);
                    mma16816(acc[mt][nt], afl, bfh[nt]);
                    mma16816(acc[mt][nt], afh, bfl[nt]);
                }
            }
        }
        __syncthreads();
    }

    // epilogue
#pragma unroll
    for (int mt = 0; mt < 4; mt++) {
#pragma unroll
        for (int g = 0; g < 2; g++) {
            int r = row0 + warp_m * 64 + mt * 16 + (lane >> 2) + g * 8;
            if (r >= M) continue;
#pragma unroll
            for (int nt = 0; nt < 4; nt++) {
                int cbase = col0 + warp_n * 32 + nt * 8 + ((lane & 3) << 1);
#pragma unroll
                for (int t = 0; t < 2; t++) {
                    int c = cbase + t;
                    float v = acc[mt][nt][g * 2 + t];
                    if (bias) v += bias[c];
                    if (act)  v = v * normcdff(v);     // exact GELU
                    if (res)  v += res[(size_t)r * N + c];
                    size_t o = (size_t)r * N + c;
                    if (C) C[o] = v;
                    if (Chi) {
                        __nv_bfloat16 hi = __float2bfloat16(v);
                        Chi[o] = hi;
                        Clo[o] = __float2bfloat16(v - __bfloat162float(hi));
                    }
                }
            }
        }
    }
}

// ---------------- attention scores: S = Q K^T / 8  (split-bf16 HMMA) ----
#define SC_SMEM (4*128*144)
__global__ __launch_bounds__(256) void attn_scores_mma()
{
    extern __shared__ char smem[];
    const int tid = threadIdx.x;
    const int wid = tid >> 5, lane = tid & 31;
    const int warp_m = wid >> 2;            // 0..1 (64 q-rows)
    const int warp_n = wid & 3;             // 0..3 (32 keys)
    const int key0 = blockIdx.x * 128, q0 = blockIdx.y * 128;
    const int bh = blockIdx.z;

    char* Qh = smem;
    char* Kh = smem + 36864;

#pragma unroll
    for (int i = 0; i < 4; i++) {
        int idx = i * 256 + tid;          // 0..1023
        int ar = idx >> 3, ac = idx & 7;  // row 0..127, chunk 0..7
        int qr = q0 + ar;
        bool vq = qr < SEQL;
        size_t qo = ((size_t)bh * SEQL + (vq ? qr : 0)) * DHEAD + ac * 8;
        uint32 dq = smaddr(Qh + ar * 144 + ac * 16);
        cpasync16(dq,         g_qh + qo, vq);
        cpasync16(dq + 18432, g_ql + qo, vq);
        int kr = key0 + ar;
        bool vk = kr < SEQL;
        size_t ko = ((size_t)bh * SEQL + (vk ? kr : 0)) * DHEAD + ac * 8;
        uint32 dk = smaddr(Kh + ar * 144 + ac * 16);
        cpasync16(dk,         g_kh + ko, vk);
        cpasync16(dk + 18432, g_kl + ko, vk);
    }
    asm volatile("cp.async.commit_group;" ::: "memory");
    asm volatile("cp.async.wait_group 0;" ::: "memory");
    __syncthreads();

    float acc[4][4][4];
#pragma unroll
    for (int i = 0; i < 4; i++)
#pragma unroll
        for (int j = 0; j < 4; j++)
#pragma unroll
            for (int e = 0; e < 4; e++) acc[i][j][e] = 0.f;

#pragma unroll
    for (int kk = 0; kk < 64; kk += 16) {
        uint32 bfh[4][2], bfl[4][2];
        int koff = kk + (((lane >> 3) & 1) << 3);
#pragma unroll
        for (int nt = 0; nt < 4; nt++) {
            int nr = warp_n * 32 + nt * 8 + (lane & 7);
            uint32 ba = smaddr(Kh + nr * 144 + koff * 2);
            ldmx2(bfh[nt], ba);
            ldmx2(bfl[nt], ba + 18432);
        }
#pragma unroll
        for (int mt = 0; mt < 4; mt++) {
            int ar = warp_m * 64 + mt * 16 + (lane & 15);
            int ac = kk + ((lane >> 4) << 3);
            uint32 aa = smaddr(Qh + ar * 144 + ac * 2);
            uint32 afh[4], afl[4];
            ldmx4(afh, aa);
            ldmx4(afl, aa + 18432);
#pragma unroll
            for (int nt = 0; nt < 4; nt++) {
                mma16816(acc[mt][nt], afh, bfh[nt]);
                mma16816(acc[mt][nt], afl, bfh[nt]);
                mma16816(acc[mt][nt], afh, bfl[nt]);
            }
        }
    }

    float* S = g_att + (size_t)bh * SEQL * SPAD;
#pragma unroll
    for (int mt = 0; mt < 4; mt++) {
#pragma unroll
        for (int g = 0; g < 2; g++) {
            int r = q0 + warp_m * 64 + mt * 16 + (lane >> 2) + g * 8;
            if (r >= SEQL) continue;
#pragma unroll
            for (int nt = 0; nt < 4; nt++) {
                int cbase = key0 + warp_n * 32 + nt * 8 + ((lane & 3) << 1);
#pragma unroll
                for (int t = 0; t < 2; t++) {
                    int c = cbase + t;
                    if (c < SEQL)
                        S[(size_t)r * SPAD + c] = acc[mt][nt][g * 2 + t] * 0.125f;
                }
            }
        }
    }
}

// ---------------- softmax: fp32 logits -> split bf16 probs (padded zeros) ----
__global__ __launch_bounds__(128) void softmax_k()
{
    size_t row = blockIdx.x;
    const float* p = g_att + row * SPAD;
    __nv_bfloat16* ph = g_ph + row * SPAD;
    __nv_bfloat16* pl = g_pl + row * SPAD;
    int tid = threadIdx.x;
    float vals[5];
    int cnt = 0;
    float lmax = -3.4e38f;
    for (int i = tid; i < SEQL; i += 128) { float v = p[i]; vals[cnt++] = v; lmax = fmaxf(lmax, v); }
#pragma unroll
    for (int o = 16; o; o >>= 1) lmax = fmaxf(lmax, __shfl_xor_sync(0xffffffffu, lmax, o));
    __shared__ float sm[4], ss[4];
    if ((tid & 31) == 0) sm[tid >> 5] = lmax;
    __syncthreads();
    lmax = fmaxf(fmaxf(sm[0], sm[1]), fmaxf(sm[2], sm[3]));
    float lsum = 0.f;
    for (int j = 0; j < cnt; j++) { vals[j] = expf(vals[j] - lmax); lsum += vals[j]; }
#pragma unroll
    for (int o = 16; o; o >>= 1) lsum += __shfl_xor_sync(0xffffffffu, lsum, o);
    if ((tid & 31) == 0) ss[tid >> 5] = lsum;
    __syncthreads();
    lsum = ss[0] + ss[1] + ss[2] + ss[3];
    float inv = 1.f / lsum;
    cnt = 0;
    for (int i = tid; i < SEQL; i += 128) {
        float v = vals[cnt++] * inv;
        __nv_bfloat16 hi = __float2bfloat16(v);
        ph[i] = hi;
        pl[i] = __float2bfloat16(v - __bfloat162float(hi));
    }
    for (int i = SEQL + tid; i < SPAD; i += 128) { ph[i] = __float2bfloat16(0.f); pl[i] = __float2bfloat16(0.f); }
}

// ---------------- AV: Z += P @ V  (split-bf16 HMMA, fused residual add) ----
#define AV_SMEM (2*128*272 + 2*128*144)
__global__ __launch_bounds__(256) void attn_av_mma()
{
    extern __shared__ char smem[];
    const int tid = threadIdx.x;
    const int wid = tid >> 5, lane = tid & 31;
    const int warp_m = wid & 3;             // 0..3 (32 q-rows)
    const int warp_n = wid >> 2;            // 0..1 (32 d-cols)
    const int q0 = blockIdx.x * 128;
    const int bh = blockIdx.y;

    char* Ph = smem;
    char* Vh = smem + 69632;

    float acc[2][4][4];
#pragma unroll
    for (int i = 0; i < 2; i++)
#pragma unroll
        for (int j = 0; j < 4; j++)
#pragma unroll
            for (int e = 0; e < 4; e++) acc[i][j][e] = 0.f;

    for (int kt = 0; kt < 5; kt++) {
#pragma unroll
        for (int i = 0; i < 8; i++) {
            int idx = i * 256 + tid;
            int ar = idx >> 4, ac = idx & 15;
            int qr = q0 + ar;
            bool v = qr < SEQL;
            size_t po = ((size_t)bh * SEQL + (v ? qr : 0)) * SPAD + kt * 128 + ac * 8;
            uint32 dp = smaddr(Ph + ar * 272 + ac * 16);
            cpasync16(dp,         g_ph + po, v);
            cpasync16(dp + 34816, g_pl + po, v);
        }
#pragma unroll
        for (int i = 0; i < 4; i++) {
            int idx = i * 256 + tid;          // 0..1023
            int ar = idx >> 3, ac = idx & 7;
            size_t vo = ((size_t)bh * SPAD + kt * 128 + ar) * DHEAD + ac * 8;
            uint32 dv = smaddr(Vh + ar * 144 + ac * 16);
            cpasync16(dv,         g_vh + vo, true);
            cpasync16(dv + 18432, g_vl + vo, true);
        }
        asm volatile("cp.async.commit_group;" ::: "memory");
        asm volatile("cp.async.wait_group 0;" ::: "memory");
        __syncthreads();

#pragma unroll
        for (int kk = 0; kk < 128; kk += 16) {
            uint32 bfh[4][2], bfl[4][2];
            int br = kk + (lane & 7) + (((lane >> 3) & 1) << 3);
#pragma unroll
            for (int nt = 0; nt < 4; nt++) {
                int bc = warp_n * 32 + nt * 8;
                uint32 ba = smaddr(Vh + br * 144 + bc * 2);
                ldmx2t(bfh[nt], ba);
                ldmx2t(bfl[nt], ba + 18432);
            }
#pragma unroll
            for (int mt = 0; mt < 2; mt++) {
                int ar = warp_m * 32 + mt * 16 + (lane & 15);
                int ac = kk + ((lane >> 4) << 3);
                uint32 aa = smaddr(Ph + ar * 272 + ac * 2);
                uint32 afh[4], afl[4];
                ldmx4(afh, aa);
                ldmx4(afl, aa + 34816);
#pragma unroll
                for (int nt = 0; nt < 4; nt++) {
                    mma16816(acc[mt][nt], afh, bfh[nt]);
                    mma16816(acc[mt][nt], afl, bfh[nt]);
                    mma16816(acc[mt][nt], afh, bfl[nt]);
                }
            }
        }
        __syncthreads();
    }

    // epilogue: fused residual add into g_z
    int b = bh / NHEAD, h = bh % NHEAD;
#pragma unroll
    for (int mt = 0; mt < 2; mt++) {
#pragma unroll
        for (int g = 0; g < 2; g++) {
            int r = q0 + warp_m * 32 + mt * 16 + (lane >> 2) + g * 8;
            if (r >= SEQL) continue;
            size_t zbase = ((size_t)(b * SEQL + r)) * DMODEL + h * DHEAD;
#pragma unroll
            for (int nt = 0; nt < 4; nt++) {
                int cbase = warp_n * 32 + nt * 8 + ((lane & 3) << 1);
#pragma unroll
                for (int t = 0; t < 2; t++)
                    g_z[zbase + cbase + t] += acc[mt][nt][g * 2 + t];
            }
        }
    }
}

// ---------------- layernorm: writes bf16 hi/lo ----------------
__global__ __launch_bounds__(256) void layernorm_split_k(
    const float* __restrict__ x, __nv_bfloat16* __restrict__ yh,
    __nv_bfloat16* __restrict__ yl,
    const float* __restrict__ s, const float* __restrict__ b)
{
    int row = blockIdx.x;
    const float* xr = x + (size_t)row * DMODEL;
    int tid = threadIdx.x;
    float v0 = xr[tid], v1 = xr[tid + 256], v2 = xr[tid + 512];
    float sum = v0 + v1 + v2;
    float sq  = fmaf(v0, v0, fmaf(v1, v1, v2 * v2));
#pragma unroll
    for (int o = 16; o; o >>= 1) {
        sum += __shfl_xor_sync(0xffffffffu, sum, o);
        sq  += __shfl_xor_sync(0xffffffffu, sq,  o);
    }
    __shared__ float s1[8], s2[8];
    if ((tid & 31) == 0) { s1[tid >> 5] = sum; s2[tid >> 5] = sq; }
    __syncthreads();
    float tsum = 0.f, tsq = 0.f;
#pragma unroll
    for (int i = 0; i < 8; i++) { tsum += s1[i]; tsq += s2[i]; }
    float m = tsum * (1.f / DMODEL);
    float var = tsq * (1.f / DMODEL) - m * m;
    float r = rsqrtf(var + 1e-5f);
    size_t base = (size_t)row * DMODEL;
#pragma unroll
    for (int p = 0; p < 3; p++) {
        int i = tid + p * 256;
        float v = (p == 0 ? v0 : (p == 1 ? v1 : v2));
        float y = (v - m) * r * s[i] + b[i];
        __nv_bfloat16 hi = __float2bfloat16(y);
        yh[base + i] = hi;
        yl[base + i] = __float2bfloat16(y - __bfloat162float(hi));
    }
}

// fp32-output layernorm (head)
__global__ __launch_bounds__(256) void layernorm_k(
    const float* __restrict__ x, float* __restrict__ y,
    const float* __restrict__ s, const float* __restrict__ b)
{
    int row = blockIdx.x;
    const float* xr = x + (size_t)row * DMODEL;
    float* yr = y + (size_t)row * DMODEL;
    int tid = threadIdx.x;
    float v0 = xr[tid], v1 = xr[tid + 256], v2 = xr[tid + 512];
    float sum = v0 + v1 + v2;
    float sq  = fmaf(v0, v0, fmaf(v1, v1, v2 * v2));
#pragma unroll
    for (int o = 16; o; o >>= 1) {
        sum += __shfl_xor_sync(0xffffffffu, sum, o);
        sq  += __shfl_xor_sync(0xffffffffu, sq,  o);
    }
    __shared__ float s1[8], s2[8];
    if ((tid & 31) == 0) { s1[tid >> 5] = sum; s2[tid >> 5] = sq; }
    __syncthreads();
    float tsum = 0.f, tsq = 0.f;
#pragma unroll
    for (int i = 0; i < 8; i++) { tsum += s1[i]; tsq += s2[i]; }
    float m = tsum * (1.f / DMODEL);
    float var = tsq * (1.f / DMODEL) - m * m;
    float r = rsqrtf(var + 1e-5f);
    yr[tid]       = (v0 - m) * r * s[tid]       + b[tid];
    yr[tid + 256] = (v1 - m) * r * s[tid + 256] + b[tid + 256];
    yr[tid + 512] = (v2 - m) * r * s[tid + 512] + b[tid + 512];
}

// ---------------- embed assemble ----------------
__global__ __launch_bounds__(256) void assemble_k(
    const float* __restrict__ pos_emb, const float* __restrict__ strain_emb,
    const float* __restrict__ cls_token)
{
    int idx = blockIdx.x * 256 + threadIdx.x;
    int bt = idx / DMODEL;
    int d = idx - bt * DMODEL;
    int b = bt / SEQL;
    int t = bt - b * SEQL;
    float v = pos_emb[(size_t)t * DMODEL + d];
    if (t < STLEN) v += strain_emb[(size_t)t * DMODEL + d];
    else           v += g_ff[((size_t)(8192 + b * NPATCH2 + (t - STLEN))) * DMODEL + d];
    if (t == 0)    v += cls_token[d];
    else           v += g_ff[((size_t)(b * NPATCH1 + (t - 1))) * DMODEL + d];
    g_z[idx] = v;
}

// ---------------- qkv de-interleave + bf16 split ----------------
__global__ __launch_bounds__(256) void qkv_split_k()
{
    int t = blockIdx.x * 256 + threadIdx.x;       // NBH*SEQL*DHEAD
    int d = t & (DHEAD - 1);
    int n = (t >> 6) % SEQL;
    int bh = t / (SEQL * DHEAD);
    int h = bh % NHEAD, b = bh / NHEAD;
    size_t src = ((size_t)(b * SEQL + n)) * (3 * DMODEL) + h * (DHEAD * 3) + d * 3;
    float q = g_qkv[src], k = g_qkv[src + 1], v = g_qkv[src + 2];
    __nv_bfloat16 qhv = __float2bfloat16(q);
    __nv_bfloat16 khv = __float2bfloat16(k);
    __nv_bfloat16 vhv = __float2bfloat16(v);
    g_qh[t] = qhv; g_ql[t] = __float2bfloat16(q - __bfloat162float(qhv));
    g_kh[t] = khv; g_kl[t] = __float2bfloat16(k - __bfloat162float(khv));
    size_t vi = ((size_t)bh * SPAD + n) * DHEAD + d;
    g_vh[vi] = vhv; g_vl[vi] = __float2bfloat16(v - __bfloat162float(vhv));
}

// ---------------- mean pool over tokens ----------------
__global__ __launch_bounds__(256) void pool_k()
{
    int idx = blockIdx.x * 256 + threadIdx.x;
    int b = idx / DMODEL, d = idx - b * DMODEL;
    const float* p = g_z + (size_t)b * SEQL * DMODEL + d;
    float s = 0.f;
    for (int n = 0; n < SEQL; n++) s += p[(size_t)n * DMODEL];
    g_pool[idx] = s * (1.f / SEQL);
}

// ---------------- tiny head GEMM ----------------
__global__ void small_gemm_k(const float* __restrict__ A, const float* __restrict__ W,
                             const float* __restrict__ bias, float* __restrict__ C,
                             int N, int K)
{
    int m = blockIdx.x, n = threadIdx.x;
    if (n >= N) return;
    float s = bias[n];
    const float* a = A + (size_t)m * K;
    for (int k = 0; k < K; k++) s = fmaf(a[k], W[(size_t)k * N + n], s);
    C[(size_t)m * N + n] = s;
}

// ---------------- launch ----------------
extern "C" void kernel_launch(void* const* d_in, const int* in_sizes, int n_in,
                              void* d_out, int out_size)
{
    const float* input1     = (const float*)d_in[0];
    const float* input2     = (const float*)d_in[1];
    const float* proj_w     = (const float*)d_in[2];
    const float* proj_b     = (const float*)d_in[3];
    const float* cls_token  = (const float*)d_in[4];
    const float* pos_emb    = (const float*)d_in[5];
    const float* strain_emb = (const float*)d_in[6];
    const float* ln1_s      = (const float*)d_in[7];
    const float* ln1_b      = (const float*)d_in[8];
    const float* wqkv       = (const float*)d_in[9];
    const float* ln2_s      = (const float*)d_in[10];
    const float* ln2_b      = (const float*)d_in[11];
    const float* fc1_w      = (const float*)d_in[12];
    const float* fc1_b      = (const float*)d_in[13];
    const float* fc2_w      = (const float*)d_in[14];
    const float* fc2_b      = (const float*)d_in[15];
    const float* hn_s       = (const float*)d_in[16];
    const float* hn_b       = (const float*)d_in[17];
    const float* h1_w       = (const float*)d_in[18];
    const float* h1_b       = (const float*)d_in[19];
    const float* h2_w       = (const float*)d_in[20];
    const float* h2_b       = (const float*)d_in[21];
    const float* h3_w       = (const float*)d_in[22];
    const float* h3_b       = (const float*)d_in[23];

    float *z, *qkv, *ff, *pool, *hln, *h1, *h2;
    __nv_bfloat16 *lnh, *lnl, *ffh, *ffl, *wqh, *wql, *f1h, *f1l, *f2h, *f2l;
    __nv_bfloat16 *i1h, *i1l, *i2h, *i2l, *pwh, *pwl;
    cudaGetSymbolAddress((void**)&z,    g_z);
    cudaGetSymbolAddress((void**)&qkv,  g_qkv);
    cudaGetSymbolAddress((void**)&ff,   g_ff);
    cudaGetSymbolAddress((void**)&pool, g_pool);
    cudaGetSymbolAddress((void**)&hln,  g_hln);
    cudaGetSymbolAddress((void**)&h1,   g_h1);
    cudaGetSymbolAddress((void**)&h2,   g_h2);
    cudaGetSymbolAddress((void**)&lnh,  g_ln_h);
    cudaGetSymbolAddress((void**)&lnl,  g_ln_l);
    cudaGetSymbolAddress((void**)&ffh,  g_ff_h);
    cudaGetSymbolAddress((void**)&ffl,  g_ff_l);
    cudaGetSymbolAddress((void**)&wqh,  g_wqkv_h);
    cudaGetSymbolAddress((void**)&wql,  g_wqkv_l);
    cudaGetSymbolAddress((void**)&f1h,  g_fc1_h);
    cudaGetSymbolAddress((void**)&f1l,  g_fc1_l);
    cudaGetSymbolAddress((void**)&f2h,  g_fc2_h);
    cudaGetSymbolAddress((void**)&f2l,  g_fc2_l);
    cudaGetSymbolAddress((void**)&i1h,  g_in1h);
    cudaGetSymbolAddress((void**)&i1l,  g_in1l);
    cudaGetSymbolAddress((void**)&i2h,  g_in2h);
    cudaGetSymbolAddress((void**)&i2l,  g_in2l);
    cudaGetSymbolAddress((void**)&pwh,  g_pwh);
    cudaGetSymbolAddress((void**)&pwl,  g_pwl);

    cudaFuncSetAttribute(mma_gemm, cudaFuncAttributeMaxDynamicSharedMemorySize, MG_SMEM);
    cudaFuncSetAttribute(attn_scores_mma, cudaFuncAttributeMaxDynamicSharedMemorySize, SC_SMEM);
    cudaFuncSetAttribute(attn_av_mma, cudaFuncAttributeMaxDynamicSharedMemorySize, AV_SMEM);

    const int TOK = TOKENS;
    const int ELEM_BLKS = (TOK * DMODEL) / 256;

    // ---- input / proj_w splits, then patch embed via tensor cores ----
    {
        int ni1 = BATCH * NPATCH1 * PATCHE;
        int ni2 = BATCH * NPATCH2 * PATCHE;
        int npw = PATCHE * DMODEL;
        split_k<<<(ni1 + 255) / 256, 256>>>(input1, i1h, i1l, ni1);
        split_k<<<(ni2 + 255) / 256, 256>>>(input2, i2h, i2l, ni2);
        split_k<<<(npw + 255) / 256, 256>>>(proj_w, pwh, pwl, npw);
    }
    mma_gemm<<<dim3(DMODEL / 128, (BATCH * NPATCH1) / 128), 256, MG_SMEM>>>(
        i1h, i1l, pwh, pwl, ff, proj_b, nullptr, nullptr, nullptr,
        BATCH * NPATCH1, DMODEL, PATCHE, 0);
    mma_gemm<<<dim3(DMODEL / 128, (BATCH * NPATCH2) / 128), 256, MG_SMEM>>>(
        i2h, i2l, pwh, pwl, ff + (size_t)BATCH * NPATCH1 * DMODEL, proj_b, nullptr,
        nullptr, nullptr, BATCH * NPATCH2, DMODEL, PATCHE, 0);

    // ---- weight splits ----
    {
        int n1 = NLAYER * DMODEL * 3 * DMODEL;
        int n2 = NLAYER * DMODEL * FFDIM;
        split_k<<<(n1 + 255) / 256, 256>>>(wqkv,  wqh, wql, n1);
        split_k<<<(n2 + 255) / 256, 256>>>(fc1_w, f1h, f1l, n2);
        split_k<<<(n2 + 255) / 256, 256>>>(fc2_w, f2h, f2l, n2);
    }

    assemble_k<<<ELEM_BLKS, 256>>>(pos_emb, strain_emb, cls_token);

    const int MB = (TOK + 127) / 128;   // 65
    const int QT = (SEQL + 127) / 128;  // 5

    // ---- transformer layers ----
    for (int l = 0; l < NLAYER; l++) {
        layernorm_split_k<<<TOK, 256>>>(z, lnh, lnl, ln1_s + l * DMODEL, ln1_b + l * DMODEL);
        mma_gemm<<<dim3((3 * DMODEL) / 128, MB), 256, MG_SMEM>>>(
            lnh, lnl, wqh + (size_t)l * DMODEL * 3 * DMODEL, wql + (size_t)l * DMODEL * 3 * DMODEL,
            qkv, nullptr, nullptr, nullptr, nullptr, TOK, 3 * DMODEL, DMODEL, 0);
        qkv_split_k<<<(NBH * SEQL * DHEAD) / 256, 256>>>();
        attn_scores_mma<<<dim3(QT, QT, NBH), 256, SC_SMEM>>>();
        softmax_k<<<NBH * SEQL, 128>>>();
        attn_av_mma<<<dim3(QT, NBH), 256, AV_SMEM>>>();     // fused residual add
        layernorm_split_k<<<TOK, 256>>>(z, lnh, lnl, ln2_s + l * DMODEL, ln2_b + l * DMODEL);
        mma_gemm<<<dim3(FFDIM / 128, MB), 256, MG_SMEM>>>(
            lnh, lnl, f1h + (size_t)l * DMODEL * FFDIM, f1l + (size_t)l * DMODEL * FFDIM,
            nullptr, fc1_b + l * FFDIM, nullptr, ffh, ffl, TOK, FFDIM, DMODEL, 1);
        mma_gemm<<<dim3(DMODEL / 128, MB), 256, MG_SMEM>>>(
            ffh, ffl, f2h + (size_t)l * FFDIM * DMODEL, f2l + (size_t)l * FFDIM * DMODEL,
            z, fc2_b + l * DMODEL, z, nullptr, nullptr, TOK, DMODEL, FFDIM, 0);
    }

    // ---- head ----
    pool_k<<<(BATCH * DMODEL) / 256, 256>>>();
    layernorm_k<<<BATCH, 256>>>(pool, hln, hn_s, hn_b);
    small_gemm_k<<<BATCH, 256>>>(hln, h1_w, h1_b, h1, 256, DMODEL);
    small_gemm_k<<<BATCH, 64>>>(h1, h2_w, h2_b, h2, 64, 256);
    small_gemm_k<<<BATCH, 32>>>(h2, h3_w, h3_b, (float*)d_out, 1, 64);
}